// round 1
// baseline (speedup 1.0000x reference)
#include <cuda_runtime.h>
#include <math.h>
#include <math_constants.h>

#define Bn  16
#define Cn  684
#define Hn  32
#define Wn  128
#define HIDn 256
#define An  512
#define HWn 4096
#define NTAP 121

// ---- scratch (device globals; no allocation allowed) ----
__device__ float g_query[Bn * An];          // [b][a]
__device__ float g_weff[NTAP * An];         // [tap][a]  (fused W_attn @ W_attconv)
__device__ float g_epart[4 * Bn * HWn];     // [chunk][b][pos] deterministic partials
__device__ float g_alpha[Bn * HWn];         // softmax result for context kernel

// ---------------- query = hidden @ W_hidden^T + b_hidden ----------------
__global__ void k_query(const float* __restrict__ hidden,
                        const float* __restrict__ Wh,
                        const float* __restrict__ bh) {
    __shared__ float sh[HIDn];
    int b = blockIdx.x, tid = threadIdx.x;
    if (tid < HIDn) sh[tid] = hidden[b * HIDn + tid];
    __syncthreads();
    for (int a = tid; a < An; a += blockDim.x) {
        float s = bh[a];
        const float* w = Wh + (size_t)a * HIDn;
        #pragma unroll 8
        for (int k = 0; k < HIDn; k++) s = fmaf(w[k], sh[k], s);
        g_query[b * An + a] = s;
    }
}

// ---------------- Weff[tap][a] = sum_k W_attn[a][k] * W_attconv[k][tap] ----------------
// grid 32 (a-chunks of 16), block 256, 32KB static smem
__global__ void k_weff(const float* __restrict__ Wattn,
                       const float* __restrict__ Wconv) {
    __shared__ float sa[16 * 512];
    int chunk = blockIdx.x, tid = threadIdx.x;
    for (int i = tid; i < 16 * 512; i += 256)
        sa[i] = Wattn[(size_t)chunk * 16 * 512 + i];
    __syncthreads();
    for (int o = tid; o < 16 * NTAP; o += 256) {
        int al = o / NTAP, tap = o % NTAP;
        float s = 0.f;
        #pragma unroll 8
        for (int k = 0; k < 512; k++)
            s = fmaf(sa[al * 512 + k], Wconv[(size_t)k * NTAP + tap], s);
        g_weff[tap * An + chunk * 16 + al] = s;
    }
}

// ---------------- energy[b,h,w] = sum_a W_alpha[a]*tanh(q + cov + cft + cmt) ----------------
// grid (4 a-chunks, H, B), block 128 (thread = one a within chunk)
__global__ void __launch_bounds__(128) k_energy(
    const float* __restrict__ cft,     // [b, A, h, w]
    const float* __restrict__ cmt,     // [b, h, w, A]
    const float* __restrict__ asum,    // [b, 1, h, w]
    const float* __restrict__ walpha)  // [A]
{
    __shared__ float s_asum[11][144];  // padded alpha_sum window (rows h-5..h+5)
    __shared__ float s_we[4][Wn];      // per-warp energy partials

    const int chunk = blockIdx.x, h = blockIdx.y, b = blockIdx.z;
    const int tid = threadIdx.x;
    const int a = chunk * 128 + tid;
    const int warp = tid >> 5, lane = tid & 31;

    for (int i = tid; i < 11 * 144; i += 128) {
        int r = i / 144, c = i % 144;
        int gh = h - 5 + r, gw = c - 5;
        float v = 0.f;
        if (gh >= 0 && gh < Hn && gw >= 0 && gw < Wn)
            v = asum[(size_t)b * HWn + gh * Wn + gw];
        s_asum[r][c] = v;
    }
    __syncthreads();

    // Weff row for this 'a' into registers (coalesced: lanes = consecutive a)
    float wf[NTAP];
    #pragma unroll
    for (int t = 0; t < NTAP; t++) wf[t] = g_weff[t * An + a];

    const float q  = g_query[b * An + a];
    const float wa = walpha[a];

    const float* cft_row = cft + (((size_t)b * An + a) * Hn + h) * Wn;
    const float* cmt_row = cmt + (((size_t)b * Hn + h) * Wn) * An + a;

    for (int w = 0; w < Wn; w++) {
        float cov = 0.f;
        #pragma unroll
        for (int i = 0; i < 11; i++)
            #pragma unroll
            for (int j = 0; j < 11; j++)
                cov = fmaf(wf[i * 11 + j], s_asum[i][w + j], cov);

        float sc = q + cov + __ldg(cft_row + w) + __ldg(cmt_row + (size_t)w * An);
        float e = wa * tanhf(sc);

        #pragma unroll
        for (int off = 16; off; off >>= 1)
            e += __shfl_down_sync(0xffffffffu, e, off);
        if (lane == 0) s_we[warp][w] = e;
    }
    __syncthreads();

    // deterministic cross-warp combine
    for (int w = tid; w < Wn; w += 128) {
        float e = s_we[0][w] + s_we[1][w] + s_we[2][w] + s_we[3][w];
        g_epart[(((size_t)chunk * Bn + b) * Hn + h) * Wn + w] = e;
    }
}

// ---------------- per-batch softmax + alpha outputs ----------------
// grid B, block 256. Writes alpha and alpha_sum_new into d_out, alpha into g_alpha.
__global__ void k_softmax(const float* __restrict__ asum,
                          const int* __restrict__ mask,
                          float* __restrict__ out) {
    __shared__ float se[HWn];   // 16KB
    __shared__ float red[256];
    const int b = blockIdx.x, tid = threadIdx.x;

    float mx = -CUDART_INF_F;
    for (int p = tid; p < HWn; p += 256) {
        float e = g_epart[(0 * Bn + b) * HWn + p]
                + g_epart[(1 * Bn + b) * HWn + p]
                + g_epart[(2 * Bn + b) * HWn + p]
                + g_epart[(3 * Bn + b) * HWn + p];
        if (mask[b * HWn + p] == 0) e = -CUDART_INF_F;
        se[p] = e;
        mx = fmaxf(mx, e);
    }
    red[tid] = mx; __syncthreads();
    for (int s = 128; s; s >>= 1) {
        if (tid < s) red[tid] = fmaxf(red[tid], red[tid + s]);
        __syncthreads();
    }
    mx = red[0]; __syncthreads();

    float sum = 0.f;
    for (int p = tid; p < HWn; p += 256) {
        float ex = expf(se[p] - mx);
        se[p] = ex;
        sum += ex;
    }
    red[tid] = sum; __syncthreads();
    for (int s = 128; s; s >>= 1) {
        if (tid < s) red[tid] += red[tid + s];
        __syncthreads();
    }
    sum = red[0]; __syncthreads();

    const float inv = 1.f / sum;
    float* out_alpha = out + Bn * Cn;
    float* out_asum  = out + Bn * Cn + Bn * HWn;
    for (int p = tid; p < HWn; p += 256) {
        float al = se[p] * inv;
        g_alpha[b * HWn + p] = al;
        out_alpha[b * HWn + p] = al;
        out_asum[b * HWn + p] = al + asum[b * HWn + p];
    }
}

// ---------------- context[b][c] = sum_p alpha[b][p] * cnn[b][c][p] ----------------
// grid (C, B), block 256
__global__ void k_context(const float* __restrict__ cnn,
                          float* __restrict__ out) {
    const int c = blockIdx.x, b = blockIdx.y, tid = threadIdx.x;
    const float* row = cnn + ((size_t)b * Cn + c) * HWn;
    float s = 0.f;
    for (int p = tid; p < HWn; p += 256)
        s = fmaf(g_alpha[b * HWn + p], row[p], s);
    __shared__ float red[256];
    red[tid] = s; __syncthreads();
    for (int st = 128; st; st >>= 1) {
        if (tid < st) red[tid] += red[tid + st];
        __syncthreads();
    }
    if (tid == 0) out[b * Cn + c] = red[0];
}

extern "C" void kernel_launch(void* const* d_in, const int* in_sizes, int n_in,
                              void* d_out, int out_size) {
    const float* cnn     = (const float*)d_in[0];   // [16,684,32,128]
    const float* cft     = (const float*)d_in[1];   // [16,512,32,128]
    const float* hidden  = (const float*)d_in[2];   // [16,256]
    const float* asum    = (const float*)d_in[3];   // [16,1,32,128]
    const int*   mask    = (const int*)  d_in[4];   // [16,1,32,128]
    const float* cmt     = (const float*)d_in[5];   // [16,32,128,512]
    const float* Wh      = (const float*)d_in[6];   // [512,256]
    const float* bh      = (const float*)d_in[7];   // [512]
    const float* Wconv   = (const float*)d_in[8];   // [512,1,11,11]
    const float* Wattn   = (const float*)d_in[9];   // [512,512]
    const float* Walpha  = (const float*)d_in[10];  // [1,512]
    // d_in[11] = b_alpha: softmax-invariant, skipped

    float* out = (float*)d_out; // [ context 16*684 | alpha 16*4096 | alpha_sum_new 16*4096 ]

    k_query<<<Bn, 256>>>(hidden, Wh, bh);
    k_weff<<<32, 256>>>(Wattn, Wconv);
    k_energy<<<dim3(4, Hn, Bn), 128>>>(cft, cmt, asum, Walpha);
    k_softmax<<<Bn, 256>>>(asum, mask, out);
    k_context<<<dim3(Cn, Bn), 256>>>(cnn, out);
}

// round 3
// speedup vs baseline: 1.9079x; 1.9079x over previous
#include <cuda_runtime.h>
#include <cuda_bf16.h>
#include <mma.h>
#include <math.h>
#include <math_constants.h>
#include <cstdint>

using namespace nvcuda;

#define Bn  16
#define Cn  684
#define Hn  32
#define Wn  128
#define HIDn 256
#define An  512
#define HWn 4096
#define NTAP 121

// ---- scratch (device globals; no allocation allowed) ----
__device__ float    g_query[Bn * An];          // [b][a]
__device__ uint32_t g_weffb[An * 64];          // bf16x2 pairs: [a][tap-pair], taps padded to 128
__device__ float    g_energy[Bn * HWn];
__device__ float    g_alpha[Bn * HWn];

// SMEM layout for k_energy (bytes)
#define LDX 136            // X row stride in bf16 elems (128 data + 8 pad)
#define LDW 136            // W row stride in bf16 elems
#define LDD 68             // D row stride in f32 elems (64 data + 4 pad)
#define SM_X   0                         // 128*136*2 = 34816
#define SM_W   34816                     // 512*136*2 = 139264
#define SM_D   (SM_W + 139264)           // 128*68*4 = 34816
#define SM_Q   (SM_D + 34816)            // 512*4
#define SM_WA  (SM_Q + 2048)             // 512*4
#define SM_TOT (SM_WA + 2048)            // 212992 bytes

// fast tanh: 1 - 2/(e^{2|x|}+1), via ex2.approx + rcp.approx (abs err ~2e-7)
__device__ __forceinline__ float fast_tanh(float x) {
    float ax = fabsf(x);
    float t = ax * 2.885390081777927f;  // 2*log2(e)
    float e, r;
    asm("ex2.approx.f32 %0, %1;" : "=f"(e) : "f"(t));
    asm("rcp.approx.f32 %0, %1;" : "=f"(r) : "f"(e + 1.0f));
    float y = fmaf(-2.0f, r, 1.0f);
    return copysignf(y, x);
}

// ---------------- query = hidden @ W_hidden^T + b_hidden ----------------
__global__ void k_query(const float* __restrict__ hidden,
                        const float* __restrict__ Wh,
                        const float* __restrict__ bh) {
    __shared__ float sh[HIDn];
    int b = blockIdx.x, tid = threadIdx.x;
    if (tid < HIDn) sh[tid] = hidden[b * HIDn + tid];
    __syncthreads();
    for (int a = tid; a < An; a += blockDim.x) {
        float s = bh[a];
        const float* w = Wh + (size_t)a * HIDn;
        #pragma unroll 8
        for (int k = 0; k < HIDn; k++) s = fmaf(w[k], sh[k], s);
        g_query[b * An + a] = s;
    }
}

// ---------------- Weff[a][tap] = sum_k W_attn[a][k] * W_attconv[k][tap], to bf16 pairs ----------------
__global__ void k_weff(const float* __restrict__ Wattn,
                       const float* __restrict__ Wconv) {
    __shared__ float sa[16 * 512];
    int chunk = blockIdx.x, tid = threadIdx.x;
    for (int i = tid; i < 16 * 512; i += 256)
        sa[i] = Wattn[(size_t)chunk * 16 * 512 + i];
    __syncthreads();
    for (int o = tid; o < 16 * 64; o += 256) {
        int al = o / 64, pr = o % 64;
        float v0 = 0.f, v1 = 0.f;
        int t0 = pr * 2, t1 = pr * 2 + 1;
        if (t0 < NTAP) {
            #pragma unroll 8
            for (int k = 0; k < 512; k++)
                v0 = fmaf(sa[al * 512 + k], Wconv[(size_t)k * NTAP + t0], v0);
        }
        if (t1 < NTAP) {
            #pragma unroll 8
            for (int k = 0; k < 512; k++)
                v1 = fmaf(sa[al * 512 + k], Wconv[(size_t)k * NTAP + t1], v1);
        }
        uint32_t lo = (uint32_t)__bfloat16_as_ushort(__float2bfloat16(v0));
        uint32_t hi = (uint32_t)__bfloat16_as_ushort(__float2bfloat16(v1));
        g_weffb[(chunk * 16 + al) * 64 + pr] = lo | (hi << 16);
    }
}

// ---------------- energy via wmma GEMM + fused tanh epilogue ----------------
// grid (H, B), 256 threads (8 warps). Warp w owns M-tile w (16 positions).
// 8 N-chunks of 64 'a' each: prefetch -> GEMM -> epilogue.
__global__ void __launch_bounds__(256, 1) k_energy(
    const float* __restrict__ cft,     // [b, A, h, w]
    const float* __restrict__ cmt,     // [b, h, w, A]
    const float* __restrict__ asum,    // [b, 1, h, w]
    const float* __restrict__ walpha)  // [A]
{
    extern __shared__ char smem[];
    const int h = blockIdx.x, b = blockIdx.y;
    const int tid = threadIdx.x;
    const int warp = tid >> 5;
    const int m = tid & 127;       // position
    const int half = tid >> 7;     // which 32 of the 64 a-chunk

    __nv_bfloat16* Xsm = (__nv_bfloat16*)(smem + SM_X);
    __nv_bfloat16* Wsm = (__nv_bfloat16*)(smem + SM_W);
    float*         Dsm = (float*)(smem + SM_D);
    float*         Qsm = (float*)(smem + SM_Q);
    float*         WAsm = (float*)(smem + SM_WA);

    // ---- stage X = im2col(asum) [128 pos x 128 taps] bf16 ----
    const float* arow = asum + (size_t)b * HWn;
    for (int o = tid; o < 128 * 64; o += 256) {
        int mm = o >> 6, pr = o & 63;
        uint32_t packed = 0;
        #pragma unroll
        for (int hf = 0; hf < 2; hf++) {
            int k = pr * 2 + hf;
            float v = 0.f;
            if (k < NTAP) {
                int i = k / 11, j = k % 11;
                int gh = h - 5 + i, gw = mm - 5 + j;
                if (gh >= 0 && gh < Hn && gw >= 0 && gw < Wn)
                    v = arow[gh * Wn + gw];
            }
            packed |= ((uint32_t)__bfloat16_as_ushort(__float2bfloat16(v))) << (16 * hf);
        }
        *(uint32_t*)((char*)Xsm + mm * (LDX * 2) + pr * 4) = packed;
    }
    // ---- stage W = Weffb [512 a x 128 taps] bf16 ----
    for (int o = tid; o < 512 * 64; o += 256) {
        int a = o >> 6, pr = o & 63;
        *(uint32_t*)((char*)Wsm + a * (LDW * 2) + pr * 4) = g_weffb[o];
    }
    // ---- stage q, wa ----
    for (int a = tid; a < An; a += 256) {
        Qsm[a]  = g_query[b * An + a];
        WAsm[a] = walpha[a];
    }
    __syncthreads();

    // ---- preload A fragments: warp w owns rows [16w, 16w+16) ----
    wmma::fragment<wmma::matrix_a, 16, 16, 16, __nv_bfloat16, wmma::row_major> afr[8];
    #pragma unroll
    for (int kk = 0; kk < 8; kk++)
        wmma::load_matrix_sync(afr[kk], Xsm + warp * 16 * LDX + kk * 16, LDX);

    const float* cmtp = cmt + (((size_t)b * Hn + h) * Wn + m) * An;
    const float* cftp = cft + ((size_t)b * An) * (Hn * Wn) + h * Wn + m;
    float energy = 0.f;

    for (int nc = 0; nc < 8; nc++) {
        const int a0 = nc * 64 + half * 32;

        // prefetch globals for this chunk (independent of GEMM)
        float4 cm[8];
        const float4* cmv = (const float4*)(cmtp + a0);
        #pragma unroll
        for (int i = 0; i < 8; i++) cm[i] = cmv[i];
        float cf[32];
        #pragma unroll
        for (int i = 0; i < 32; i++)
            cf[i] = __ldg(cftp + (size_t)(a0 + i) * (Hn * Wn));

        // GEMM: D[128, 64] = X @ W_chunk^T
        #pragma unroll
        for (int nt = 0; nt < 4; nt++) {
            wmma::fragment<wmma::accumulator, 16, 16, 16, float> acc;
            wmma::fill_fragment(acc, 0.0f);
            #pragma unroll
            for (int kk = 0; kk < 8; kk++) {
                wmma::fragment<wmma::matrix_b, 16, 16, 16, __nv_bfloat16, wmma::col_major> bfr;
                wmma::load_matrix_sync(bfr, Wsm + (nc * 64 + nt * 16) * LDW + kk * 16, LDW);
                wmma::mma_sync(acc, afr[kk], bfr, acc);
            }
            wmma::store_matrix_sync(Dsm + warp * 16 * LDD + nt * 16, acc, LDD, wmma::mem_row_major);
        }
        __syncthreads();

        // epilogue: thread covers (position m, a in [a0, a0+32))
        #pragma unroll
        for (int i = 0; i < 8; i++) {
            float4 d4 = *(const float4*)(Dsm + m * LDD + half * 32 + i * 4);
            float dd[4] = {d4.x, d4.y, d4.z, d4.w};
            float cc[4] = {cm[i].x, cm[i].y, cm[i].z, cm[i].w};
            #pragma unroll
            for (int j = 0; j < 4; j++) {
                int a = a0 + i * 4 + j;
                float sc = Qsm[a] + dd[j] + cf[i * 4 + j] + cc[j];
                energy = fmaf(WAsm[a], fast_tanh(sc), energy);
            }
        }
        __syncthreads();  // before Dsm is overwritten next chunk
    }

    // combine the two halves per position (Dsm free after last barrier)
    float* red = Dsm;
    red[tid] = energy;
    __syncthreads();
    if (half == 0)
        g_energy[((size_t)b * Hn + h) * Wn + m] = red[m] + red[128 + m];
}

// ---------------- per-batch softmax + alpha outputs ----------------
__global__ void k_softmax(const float* __restrict__ asum,
                          const int* __restrict__ mask,
                          float* __restrict__ out) {
    __shared__ float se[HWn];
    __shared__ float red[512];
    const int b = blockIdx.x, tid = threadIdx.x;

    float mx = -CUDART_INF_F;
    for (int p = tid; p < HWn; p += 512) {
        float e = g_energy[b * HWn + p];
        if (mask[b * HWn + p] == 0) e = -CUDART_INF_F;
        se[p] = e;
        mx = fmaxf(mx, e);
    }
    red[tid] = mx; __syncthreads();
    for (int s = 256; s; s >>= 1) {
        if (tid < s) red[tid] = fmaxf(red[tid], red[tid + s]);
        __syncthreads();
    }
    mx = red[0]; __syncthreads();

    float sum = 0.f;
    for (int p = tid; p < HWn; p += 512) {
        float ex = __expf(se[p] - mx);
        se[p] = ex;
        sum += ex;
    }
    red[tid] = sum; __syncthreads();
    for (int s = 256; s; s >>= 1) {
        if (tid < s) red[tid] += red[tid + s];
        __syncthreads();
    }
    sum = red[0]; __syncthreads();

    const float inv = 1.f / sum;
    float* out_alpha = out + Bn * Cn;
    float* out_asum  = out + Bn * Cn + Bn * HWn;
    for (int p = tid; p < HWn; p += 512) {
        float al = se[p] * inv;
        g_alpha[b * HWn + p] = al;
        out_alpha[b * HWn + p] = al;
        out_asum[b * HWn + p] = al + asum[b * HWn + p];
    }
}

// ---------------- context[b][c] = sum_p alpha[b][p] * cnn[b][c][p] ----------------
__global__ void k_context(const float* __restrict__ cnn,
                          float* __restrict__ out) {
    const int c = blockIdx.x, b = blockIdx.y, tid = threadIdx.x;
    const float4* row = (const float4*)(cnn + ((size_t)b * Cn + c) * HWn);
    const float4* al  = (const float4*)(g_alpha + b * HWn);
    float s = 0.f;
    #pragma unroll
    for (int it = 0; it < 4; it++) {
        int p = it * 256 + tid;
        float4 r = row[p], a = al[p];
        s = fmaf(a.x, r.x, s); s = fmaf(a.y, r.y, s);
        s = fmaf(a.z, r.z, s); s = fmaf(a.w, r.w, s);
    }
    __shared__ float red[256];
    red[tid] = s; __syncthreads();
    for (int st = 128; st; st >>= 1) {
        if (tid < st) red[tid] += red[tid + st];
        __syncthreads();
    }
    if (tid == 0) out[b * Cn + c] = red[0];
}

extern "C" void kernel_launch(void* const* d_in, const int* in_sizes, int n_in,
                              void* d_out, int out_size) {
    const float* cnn     = (const float*)d_in[0];   // [16,684,32,128]
    const float* cft     = (const float*)d_in[1];   // [16,512,32,128]
    const float* hidden  = (const float*)d_in[2];   // [16,256]
    const float* asum    = (const float*)d_in[3];   // [16,1,32,128]
    const int*   mask    = (const int*)  d_in[4];   // [16,1,32,128]
    const float* cmt     = (const float*)d_in[5];   // [16,32,128,512]
    const float* Wh      = (const float*)d_in[6];   // [512,256]
    const float* bh      = (const float*)d_in[7];   // [512]
    const float* Wconv   = (const float*)d_in[8];   // [512,1,11,11]
    const float* Wattn   = (const float*)d_in[9];   // [512,512]
    const float* Walpha  = (const float*)d_in[10];  // [1,512]
    // d_in[11] = b_alpha: softmax-invariant, skipped

    float* out = (float*)d_out; // [ context 16*684 | alpha 16*4096 | alpha_sum_new 16*4096 ]

    cudaFuncSetAttribute(k_energy, cudaFuncAttributeMaxDynamicSharedMemorySize, SM_TOT);

    k_query<<<Bn, 256>>>(hidden, Wh, bh);
    k_weff<<<32, 256>>>(Wattn, Wconv);
    k_energy<<<dim3(Hn, Bn), 256, SM_TOT>>>(cft, cmt, asum, Walpha);
    k_softmax<<<Bn, 512>>>(asum, mask, out);
    k_context<<<dim3(Cn, Bn), 256>>>(cnn, out);
}

// round 4
// speedup vs baseline: 3.2415x; 1.6990x over previous
#include <cuda_runtime.h>
#include <cuda_bf16.h>
#include <mma.h>
#include <math.h>
#include <math_constants.h>
#include <cstdint>

using namespace nvcuda;

#define Bn  16
#define Cn  684
#define Hn  32
#define Wn  128
#define HIDn 256
#define An  512
#define HWn 4096
#define NTAP 121

// ---- scratch (device globals; no allocation allowed) ----
__device__ float    g_query[Bn * An];          // [b][a]
__device__ uint32_t g_weffb[An * 64];          // bf16x2 pairs: [a][tap-pair], taps padded to 128
__device__ float    g_epart[2 * Bn * HWn];     // [half][b][pos]
__device__ float    g_alpha[Bn * HWn];

// k_energy SMEM layout (bytes):
//   X   [128 pos][136 taps] bf16  @ 0        (34816)
//   W   [256 a  ][136 taps] bf16  @ 34816    (69632)
//   buf [8 warps][16][20]   f32   @ 104448   (10240)
#define LDX 136
#define LDW 136
#define LDBUF 20
#define SM_X 0
#define SM_W 34816
#define SM_BUF 104448
#define SM_TOT 114688

// fast tanh: 1 - 2/(e^{2|x|}+1), via ex2.approx + rcp.approx
__device__ __forceinline__ float fast_tanh(float x) {
    float ax = fabsf(x);
    float t = ax * 2.885390081777927f;  // 2*log2(e)
    float e, r;
    asm("ex2.approx.f32 %0, %1;" : "=f"(e) : "f"(t));
    asm("rcp.approx.f32 %0, %1;" : "=f"(r) : "f"(e + 1.0f));
    float y = fmaf(-2.0f, r, 1.0f);
    return copysignf(y, x);
}

// ---------------- fused prep: query (blocks 0-15) + weff (blocks 16-47) ----------------
__global__ void k_prep(const float* __restrict__ hidden,
                       const float* __restrict__ Wh,
                       const float* __restrict__ bh,
                       const float* __restrict__ Wattn,
                       const float* __restrict__ Wconv) {
    __shared__ float sa[16 * 512];
    const int tid = threadIdx.x;
    if (blockIdx.x < 16) {
        // ---- query = hidden @ Wh^T + bh ----
        const int b = blockIdx.x;
        if (tid < HIDn) sa[tid] = hidden[b * HIDn + tid];
        __syncthreads();
        for (int a = tid; a < An; a += 256) {
            float s = bh[a];
            const float* w = Wh + (size_t)a * HIDn;
            #pragma unroll 8
            for (int k = 0; k < HIDn; k++) s = fmaf(w[k], sa[k], s);
            g_query[b * An + a] = s;
        }
    } else {
        // ---- Weff[a][tap] = sum_k Wattn[a][k] * Wconv[k][tap], bf16 pairs ----
        const int chunk = blockIdx.x - 16;
        for (int i = tid; i < 16 * 512; i += 256)
            sa[i] = Wattn[(size_t)chunk * 16 * 512 + i];
        __syncthreads();
        for (int o = tid; o < 16 * 64; o += 256) {
            int al = o / 64, pr = o % 64;
            float v0 = 0.f, v1 = 0.f;
            int t0 = pr * 2, t1 = pr * 2 + 1;
            if (t0 < NTAP) {
                #pragma unroll 8
                for (int k = 0; k < 512; k++)
                    v0 = fmaf(sa[al * 512 + k], Wconv[(size_t)k * NTAP + t0], v0);
            }
            if (t1 < NTAP) {
                #pragma unroll 8
                for (int k = 0; k < 512; k++)
                    v1 = fmaf(sa[al * 512 + k], Wconv[(size_t)k * NTAP + t1], v1);
            }
            uint32_t lo = (uint32_t)__bfloat16_as_ushort(__float2bfloat16(v0));
            uint32_t hi = (uint32_t)__bfloat16_as_ushort(__float2bfloat16(v1));
            g_weffb[(chunk * 16 + al) * 64 + pr] = lo | (hi << 16);
        }
    }
}

// ---------------- energy: D[a,pos] GEMM + fully warp-private fused epilogue ----------------
// grid (2 a-halves, H, B), 256 threads (8 warps). Warp wid owns positions [16*wid, 16*wid+16).
__global__ void __launch_bounds__(256, 2) k_energy(
    const float* __restrict__ cft,     // [b, A, h, w]
    const float* __restrict__ cmt,     // [b, h, w, A]
    const float* __restrict__ asum,    // [b, 1, h, w]
    const float* __restrict__ walpha)  // [A]
{
    extern __shared__ char smem[];
    __nv_bfloat16* Xsm = (__nv_bfloat16*)(smem + SM_X);
    __nv_bfloat16* Wsm = (__nv_bfloat16*)(smem + SM_W);

    const int half = blockIdx.x, h = blockIdx.y, b = blockIdx.z;
    const int tid = threadIdx.x, wid = tid >> 5, lane = tid & 31;

    // ---- stage X = im2col(asum) [128 pos x 128 taps] bf16 ----
    const float* arow = asum + (size_t)b * HWn;
    for (int o = tid; o < 128 * 64; o += 256) {
        int mm = o >> 6, pr = o & 63;
        uint32_t packed = 0;
        #pragma unroll
        for (int hf = 0; hf < 2; hf++) {
            int k = pr * 2 + hf;
            float v = 0.f;
            if (k < NTAP) {
                int i = k / 11, j = k % 11;
                int gh = h - 5 + i, gw = mm - 5 + j;
                if (gh >= 0 && gh < Hn && gw >= 0 && gw < Wn)
                    v = arow[gh * Wn + gw];
            }
            packed |= ((uint32_t)__bfloat16_as_ushort(__float2bfloat16(v))) << (16 * hf);
        }
        *(uint32_t*)((char*)Xsm + mm * (LDX * 2) + pr * 4) = packed;
    }
    // ---- stage W half: 256 rows x 128 taps bf16 (rows half*256..) ----
    const uint4* wsrc = (const uint4*)(g_weffb + (size_t)half * 256 * 64);
    for (int o = tid; o < 4096; o += 256) {
        int a = o >> 4, q = o & 15;   // 16 uint4 per 256B row
        *(uint4*)((char*)Wsm + a * (LDW * 2) + q * 16) = wsrc[o];
    }
    __syncthreads();

    // ---- per-warp B fragments: X columns for this warp's 16 positions ----
    const int pos0 = wid * 16;
    wmma::fragment<wmma::matrix_b, 16, 16, 16, __nv_bfloat16, wmma::col_major> bfr[8];
    #pragma unroll
    for (int kk = 0; kk < 8; kk++)
        wmma::load_matrix_sync(bfr[kk], Xsm + pos0 * LDX + kk * 16, LDX);

    float* buf = (float*)(smem + SM_BUF) + wid * (16 * LDBUF);

    // lane mappings
    const int a1 = lane >> 4, p1 = lane & 15;  // phase-1 (cft add): a = a1+2j, pos = p1
    const int a2 = lane & 15, p2 = lane >> 4;  // phase-2 (cmt+tanh): a = a2, pos = p2+2j

    float epos[8];
    #pragma unroll
    for (int j = 0; j < 8; j++) epos[j] = 0.f;

    const size_t HW = (size_t)Hn * Wn;

    for (int mt = 0; mt < 16; mt++) {
        const int A0 = half * 256 + mt * 16;

        // prefetch (sector-perfect: half-warps hit 64B runs)
        float cf[8], cm[8];
        const float* cfp = cft + (((size_t)b * An + A0 + a1) * Hn + h) * Wn + pos0 + p1;
        #pragma unroll
        for (int j = 0; j < 8; j++) cf[j] = __ldg(cfp + (size_t)(2 * j) * HW);
        const float* cmp = cmt + (((size_t)b * Hn + h) * Wn + pos0 + p2) * An + A0 + a2;
        #pragma unroll
        for (int j = 0; j < 8; j++) cm[j] = __ldg(cmp + (size_t)(2 * j) * An);
        const float q_l  = __ldg(&g_query[b * An + A0 + a2]);
        const float wa_l = __ldg(&walpha[A0 + a2]);

        // GEMM: acc[16 a x 16 pos]
        wmma::fragment<wmma::accumulator, 16, 16, 16, float> acc;
        wmma::fill_fragment(acc, 0.0f);
        #pragma unroll
        for (int kk = 0; kk < 8; kk++) {
            wmma::fragment<wmma::matrix_a, 16, 16, 16, __nv_bfloat16, wmma::row_major> afr;
            wmma::load_matrix_sync(afr, Wsm + (mt * 16) * LDW + kk * 16, LDW);
            wmma::mma_sync(acc, afr, bfr[kk], acc);
        }
        wmma::store_matrix_sync(buf, acc, LDBUF, wmma::mem_row_major);
        __syncwarp();

        // phase 1: add cft (lane owns (a1+2j, p1))
        #pragma unroll
        for (int j = 0; j < 8; j++)
            buf[(a1 + 2 * j) * LDBUF + p1] += cf[j];
        __syncwarp();

        // phase 2: + cmt + query, tanh, weighted reduce into per-pos partials
        #pragma unroll
        for (int j = 0; j < 8; j++) {
            float sc = buf[a2 * LDBUF + p2 + 2 * j] + cm[j] + q_l;
            epos[j] = fmaf(wa_l, fast_tanh(sc), epos[j]);
        }
        __syncwarp();
    }

    // reduce over the 16 a-lanes per pos (lanes differing in bits 0-3)
    #pragma unroll
    for (int j = 0; j < 8; j++) {
        #pragma unroll
        for (int s = 8; s; s >>= 1)
            epos[j] += __shfl_xor_sync(0xffffffffu, epos[j], s);
    }
    if ((lane & 15) == 0) {
        float* ep = g_epart + ((size_t)half * Bn + b) * HWn + h * Wn + pos0;
        #pragma unroll
        for (int j = 0; j < 8; j++)
            ep[p2 + 2 * j] = epos[j];
    }
}

// ---------------- per-batch softmax + alpha outputs ----------------
__global__ void k_softmax(const float* __restrict__ asum,
                          const int* __restrict__ mask,
                          float* __restrict__ out) {
    __shared__ float se[HWn];
    __shared__ float red[512];
    const int b = blockIdx.x, tid = threadIdx.x;

    float mx = -CUDART_INF_F;
    for (int p = tid; p < HWn; p += 512) {
        float e = g_epart[b * HWn + p] + g_epart[(Bn + b) * HWn + p];
        if (mask[b * HWn + p] == 0) e = -CUDART_INF_F;
        se[p] = e;
        mx = fmaxf(mx, e);
    }
    red[tid] = mx; __syncthreads();
    for (int s = 256; s; s >>= 1) {
        if (tid < s) red[tid] = fmaxf(red[tid], red[tid + s]);
        __syncthreads();
    }
    mx = red[0]; __syncthreads();

    float sum = 0.f;
    for (int p = tid; p < HWn; p += 512) {
        float ex = __expf(se[p] - mx);
        se[p] = ex;
        sum += ex;
    }
    red[tid] = sum; __syncthreads();
    for (int s = 256; s; s >>= 1) {
        if (tid < s) red[tid] += red[tid + s];
        __syncthreads();
    }
    sum = red[0]; __syncthreads();

    const float inv = 1.f / sum;
    float* out_alpha = out + Bn * Cn;
    float* out_asum  = out + Bn * Cn + Bn * HWn;
    for (int p = tid; p < HWn; p += 512) {
        float al = se[p] * inv;
        g_alpha[b * HWn + p] = al;
        out_alpha[b * HWn + p] = al;
        out_asum[b * HWn + p] = al + asum[b * HWn + p];
    }
}

// ---------------- context[b][c] = sum_p alpha[b][p] * cnn[b][c][p] ----------------
__global__ void k_context(const float* __restrict__ cnn,
                          float* __restrict__ out) {
    const int c = blockIdx.x, b = blockIdx.y, tid = threadIdx.x;
    const float4* row = (const float4*)(cnn + ((size_t)b * Cn + c) * HWn);
    const float4* al  = (const float4*)(g_alpha + b * HWn);
    float s = 0.f;
    #pragma unroll
    for (int it = 0; it < 4; it++) {
        int p = it * 256 + tid;
        float4 r = row[p], a = al[p];
        s = fmaf(a.x, r.x, s); s = fmaf(a.y, r.y, s);
        s = fmaf(a.z, r.z, s); s = fmaf(a.w, r.w, s);
    }
    __shared__ float red[256];
    red[tid] = s; __syncthreads();
    for (int st = 128; st; st >>= 1) {
        if (tid < st) red[tid] += red[tid + st];
        __syncthreads();
    }
    if (tid == 0) out[b * Cn + c] = red[0];
}

extern "C" void kernel_launch(void* const* d_in, const int* in_sizes, int n_in,
                              void* d_out, int out_size) {
    const float* cnn     = (const float*)d_in[0];   // [16,684,32,128]
    const float* cft     = (const float*)d_in[1];   // [16,512,32,128]
    const float* hidden  = (const float*)d_in[2];   // [16,256]
    const float* asum    = (const float*)d_in[3];   // [16,1,32,128]
    const int*   mask    = (const int*)  d_in[4];   // [16,1,32,128]
    const float* cmt     = (const float*)d_in[5];   // [16,32,128,512]
    const float* Wh      = (const float*)d_in[6];   // [512,256]
    const float* bh      = (const float*)d_in[7];   // [512]
    const float* Wconv   = (const float*)d_in[8];   // [512,1,11,11]
    const float* Wattn   = (const float*)d_in[9];   // [512,512]
    const float* Walpha  = (const float*)d_in[10];  // [1,512]
    // d_in[11] = b_alpha: softmax-invariant, skipped

    float* out = (float*)d_out; // [ context 16*684 | alpha 16*4096 | alpha_sum_new 16*4096 ]

    cudaFuncSetAttribute(k_energy, cudaFuncAttributeMaxDynamicSharedMemorySize, SM_TOT);

    k_prep<<<48, 256>>>(hidden, Wh, bh, Wattn, Wconv);
    k_energy<<<dim3(2, Hn, Bn), 256, SM_TOT>>>(cft, cmt, asum, Walpha);
    k_softmax<<<Bn, 512>>>(asum, mask, out);
    k_context<<<dim3(Cn, Bn), 256>>>(cnn, out);
}

// round 5
// speedup vs baseline: 3.4554x; 1.0660x over previous
#include <cuda_runtime.h>
#include <cuda_bf16.h>
#include <math.h>
#include <math_constants.h>
#include <cstdint>

#define Bn  16
#define Cn  684
#define Hn  32
#define Wn  128
#define HIDn 256
#define An  512
#define HWn 4096
#define NTAP 121

// ---- scratch (device globals; no allocation allowed) ----
__device__ float    g_query[Bn * An];          // [b][a]
__device__ uint32_t g_weffb[An * 64];          // bf16x2 pairs: [a][tap-pair], taps padded to 128
__device__ float    g_epart[2 * Bn * HWn];     // [half][b][pos]
__device__ float    g_alpha[Bn * HWn];

// k_energy SMEM layout (bytes):
//   X   [128 pos][136 taps] bf16  @ 0        (34816)
//   W   [256 a  ][136 taps] bf16  @ 34816    (69632)
//   qwa [256] float2               @ 104448   (2048)
#define LDX 136
#define LDW 136
#define SM_X 0
#define SM_W 34816
#define SM_QWA 104448
#define SM_TOT 106496

// fast tanh: 1 - 2/(e^{2|x|}+1), via ex2.approx + rcp.approx
__device__ __forceinline__ float fast_tanh(float x) {
    float ax = fabsf(x);
    float t = ax * 2.885390081777927f;  // 2*log2(e)
    float e, r;
    asm("ex2.approx.f32 %0, %1;" : "=f"(e) : "f"(t));
    asm("rcp.approx.f32 %0, %1;" : "=f"(r) : "f"(e + 1.0f));
    float y = fmaf(-2.0f, r, 1.0f);
    return copysignf(y, x);
}

__device__ __forceinline__ uint32_t smem_u32(const void* p) {
    uint32_t a;
    asm("{ .reg .u64 t; cvta.to.shared.u64 t, %1; cvt.u32.u64 %0, t; }" : "=r"(a) : "l"(p));
    return a;
}

// ---------------- fused prep: query (blocks 0-15) + weff (blocks 16-47) ----------------
__global__ void k_prep(const float* __restrict__ hidden,
                       const float* __restrict__ Wh,
                       const float* __restrict__ bh,
                       const float* __restrict__ Wattn,
                       const float* __restrict__ Wconv) {
    __shared__ float sa[16 * 512];
    const int tid = threadIdx.x;
    if (blockIdx.x < 16) {
        const int b = blockIdx.x;
        if (tid < HIDn) sa[tid] = hidden[b * HIDn + tid];
        __syncthreads();
        for (int a = tid; a < An; a += 256) {
            float s = bh[a];
            const float* w = Wh + (size_t)a * HIDn;
            #pragma unroll 8
            for (int k = 0; k < HIDn; k++) s = fmaf(w[k], sa[k], s);
            g_query[b * An + a] = s;
        }
    } else {
        const int chunk = blockIdx.x - 16;
        for (int i = tid; i < 16 * 512; i += 256)
            sa[i] = Wattn[(size_t)chunk * 16 * 512 + i];
        __syncthreads();
        for (int o = tid; o < 16 * 64; o += 256) {
            int al = o / 64, pr = o % 64;
            float v0 = 0.f, v1 = 0.f;
            int t0 = pr * 2, t1 = pr * 2 + 1;
            if (t0 < NTAP) {
                #pragma unroll 8
                for (int k = 0; k < 512; k++)
                    v0 = fmaf(sa[al * 512 + k], Wconv[(size_t)k * NTAP + t0], v0);
            }
            if (t1 < NTAP) {
                #pragma unroll 8
                for (int k = 0; k < 512; k++)
                    v1 = fmaf(sa[al * 512 + k], Wconv[(size_t)k * NTAP + t1], v1);
            }
            uint32_t lo = (uint32_t)__bfloat16_as_ushort(__float2bfloat16(v0));
            uint32_t hi = (uint32_t)__bfloat16_as_ushort(__float2bfloat16(v1));
            g_weffb[(chunk * 16 + al) * 64 + pr] = lo | (hi << 16);
        }
    }
}

// ---------------- energy: raw mma.sync m16n8k16, register-resident epilogue ----------------
// grid (2 a-halves, H, B), 256 threads (8 warps). Warp wid owns positions [16*wid, 16*wid+16).
// Acc layout per mma.m16n8k16: c0,c1:(m=g, n=tig*2,tig*2+1); c2,c3:(m=g+8, same n).
__global__ void __launch_bounds__(256, 2) k_energy(
    const float* __restrict__ cft,     // [b, A, h, w]
    const float* __restrict__ cmt,     // [b, h, w, A]
    const float* __restrict__ asum,    // [b, 1, h, w]
    const float* __restrict__ walpha)  // [A]
{
    extern __shared__ char smem[];
    __nv_bfloat16* Xsm = (__nv_bfloat16*)(smem + SM_X);
    __nv_bfloat16* Wsm = (__nv_bfloat16*)(smem + SM_W);
    float2*        QWA = (float2*)(smem + SM_QWA);

    const int half = blockIdx.x, h = blockIdx.y, b = blockIdx.z;
    const int tid = threadIdx.x, wid = tid >> 5, lane = tid & 31;
    const int g = lane >> 2, tig = lane & 3;

    // ---- stage X = im2col(asum) [128 pos x 128 taps] bf16 ----
    const float* arow = asum + (size_t)b * HWn;
    for (int o = tid; o < 128 * 64; o += 256) {
        int mm = o >> 6, pr = o & 63;
        uint32_t packed = 0;
        #pragma unroll
        for (int hf = 0; hf < 2; hf++) {
            int k = pr * 2 + hf;
            float v = 0.f;
            if (k < NTAP) {
                int i = k / 11, j = k % 11;
                int gh = h - 5 + i, gw = mm - 5 + j;
                if (gh >= 0 && gh < Hn && gw >= 0 && gw < Wn)
                    v = arow[gh * Wn + gw];
            }
            packed |= ((uint32_t)__bfloat16_as_ushort(__float2bfloat16(v))) << (16 * hf);
        }
        *(uint32_t*)((char*)Xsm + mm * (LDX * 2) + pr * 4) = packed;
    }
    // ---- stage W half: 256 a-rows x 128 taps bf16 ----
    const uint4* wsrc = (const uint4*)(g_weffb + (size_t)half * 256 * 64);
    for (int o = tid; o < 4096; o += 256) {
        int a = o >> 4, q = o & 15;
        *(uint4*)((char*)Wsm + a * (LDW * 2) + q * 16) = wsrc[o];
    }
    // ---- stage (query, walpha) pairs for this a-half ----
    for (int i = tid; i < 256; i += 256)
        QWA[i] = make_float2(g_query[b * An + half * 256 + i], walpha[half * 256 + i]);
    __syncthreads();

    // ---- B fragments (X) once: [nh][kk][2] ----
    const int pos0 = wid * 16;
    uint32_t bf[2][8][2];
    #pragma unroll
    for (int nh = 0; nh < 2; nh++) {
        const char* xrow = (const char*)Xsm + (pos0 + nh * 8 + g) * (LDX * 2);
        #pragma unroll
        for (int kk = 0; kk < 8; kk++) {
            bf[nh][kk][0] = *(const uint32_t*)(xrow + (kk * 16 + tig * 2) * 2);
            bf[nh][kk][1] = *(const uint32_t*)(xrow + (kk * 16 + tig * 2 + 8) * 2);
        }
    }

    // ldmatrix source address for A tiles (lane-dependent part fixed)
    const uint32_t a_base = smem_u32(Wsm) + (uint32_t)(lane & 15) * (LDW * 2) + (uint32_t)(lane >> 4) * 16;

    const float* cft_b = cft + ((size_t)b * An + half * 256) * (Hn * Wn) + h * Wn;
    const float* cmt_b = cmt + (((size_t)b * Hn + h) * Wn) * An + half * 256;
    const size_t HW = (size_t)Hn * Wn;

    float epos[4] = {0.f, 0.f, 0.f, 0.f};  // [nh*2 + c01] per-pos partials

    for (int mt = 0; mt < 16; mt++) {
        const int A0 = mt * 16;  // local a offset within half

        // ---- prefetch epilogue operands ----
        float2 cf[2][2];   // [nh][aoff/8]
        #pragma unroll
        for (int nh = 0; nh < 2; nh++) {
            const float* p = cft_b + (size_t)(A0 + g) * HW + pos0 + nh * 8 + tig * 2;
            cf[nh][0] = *(const float2*)p;
            cf[nh][1] = *(const float2*)(p + 8 * HW);
        }
        float cm[2][4];    // [nh][c]
        #pragma unroll
        for (int nh = 0; nh < 2; nh++) {
            const float* p = cmt_b + (size_t)(pos0 + nh * 8 + tig * 2) * An + A0 + g;
            cm[nh][0] = __ldg(p);
            cm[nh][1] = __ldg(p + An);
            cm[nh][2] = __ldg(p + 8);
            cm[nh][3] = __ldg(p + An + 8);
        }
        float2 qw0 = QWA[A0 + g], qw1 = QWA[A0 + g + 8];

        // ---- GEMM: two n-halves, 8 k-steps ----
        float c0[4] = {0.f, 0.f, 0.f, 0.f};
        float c1[4] = {0.f, 0.f, 0.f, 0.f};
        #pragma unroll
        for (int kk = 0; kk < 8; kk++) {
            uint32_t a0r, a1r, a2r, a3r;
            uint32_t addr = a_base + (uint32_t)(A0) * (LDW * 2) + (uint32_t)(kk * 32);
            asm volatile("ldmatrix.sync.aligned.m8n8.x4.shared.b16 {%0,%1,%2,%3}, [%4];"
                         : "=r"(a0r), "=r"(a1r), "=r"(a2r), "=r"(a3r) : "r"(addr));
            asm volatile("mma.sync.aligned.m16n8k16.row.col.f32.bf16.bf16.f32 "
                         "{%0,%1,%2,%3}, {%4,%5,%6,%7}, {%8,%9}, {%0,%1,%2,%3};"
                         : "+f"(c0[0]), "+f"(c0[1]), "+f"(c0[2]), "+f"(c0[3])
                         : "r"(a0r), "r"(a1r), "r"(a2r), "r"(a3r),
                           "r"(bf[0][kk][0]), "r"(bf[0][kk][1]));
            asm volatile("mma.sync.aligned.m16n8k16.row.col.f32.bf16.bf16.f32 "
                         "{%0,%1,%2,%3}, {%4,%5,%6,%7}, {%8,%9}, {%0,%1,%2,%3};"
                         : "+f"(c1[0]), "+f"(c1[1]), "+f"(c1[2]), "+f"(c1[3])
                         : "r"(a0r), "r"(a1r), "r"(a2r), "r"(a3r),
                           "r"(bf[1][kk][0]), "r"(bf[1][kk][1]));
        }

        // ---- register-resident epilogue ----
        // nh0: c0[i]: i=0:(a=g,pos tig*2) 1:(a=g,+1) 2:(a=g+8,tig*2) 3:(a=g+8,+1)
        {
            float s;
            s = c0[0] + cf[0][0].x + cm[0][0] + qw0.x; epos[0] = fmaf(qw0.y, fast_tanh(s), epos[0]);
            s = c0[1] + cf[0][0].y + cm[0][1] + qw0.x; epos[1] = fmaf(qw0.y, fast_tanh(s), epos[1]);
            s = c0[2] + cf[0][1].x + cm[0][2] + qw1.x; epos[0] = fmaf(qw1.y, fast_tanh(s), epos[0]);
            s = c0[3] + cf[0][1].y + cm[0][3] + qw1.x; epos[1] = fmaf(qw1.y, fast_tanh(s), epos[1]);
            s = c1[0] + cf[1][0].x + cm[1][0] + qw0.x; epos[2] = fmaf(qw0.y, fast_tanh(s), epos[2]);
            s = c1[1] + cf[1][0].y + cm[1][1] + qw0.x; epos[3] = fmaf(qw0.y, fast_tanh(s), epos[3]);
            s = c1[2] + cf[1][1].x + cm[1][2] + qw1.x; epos[2] = fmaf(qw1.y, fast_tanh(s), epos[2]);
            s = c1[3] + cf[1][1].y + cm[1][3] + qw1.x; epos[3] = fmaf(qw1.y, fast_tanh(s), epos[3]);
        }
    }

    // reduce over the 8 g-lanes (lane bits 2-4)
    #pragma unroll
    for (int j = 0; j < 4; j++) {
        epos[j] += __shfl_xor_sync(0xffffffffu, epos[j], 4);
        epos[j] += __shfl_xor_sync(0xffffffffu, epos[j], 8);
        epos[j] += __shfl_xor_sync(0xffffffffu, epos[j], 16);
    }
    if (lane < 4) {
        float* ep = g_epart + ((size_t)half * Bn + b) * HWn + h * Wn + pos0;
        ep[tig * 2]         = epos[0];
        ep[tig * 2 + 1]     = epos[1];
        ep[8 + tig * 2]     = epos[2];
        ep[8 + tig * 2 + 1] = epos[3];
    }
}

// ---------------- per-batch softmax + alpha outputs ----------------
__global__ void k_softmax(const float* __restrict__ asum,
                          const int* __restrict__ mask,
                          float* __restrict__ out) {
    __shared__ float se[HWn];
    __shared__ float red[1024];
    const int b = blockIdx.x, tid = threadIdx.x;

    float mx = -CUDART_INF_F;
    for (int p = tid; p < HWn; p += 1024) {
        float e = g_epart[b * HWn + p] + g_epart[(Bn + b) * HWn + p];
        if (mask[b * HWn + p] == 0) e = -CUDART_INF_F;
        se[p] = e;
        mx = fmaxf(mx, e);
    }
    red[tid] = mx; __syncthreads();
    for (int s = 512; s; s >>= 1) {
        if (tid < s) red[tid] = fmaxf(red[tid], red[tid + s]);
        __syncthreads();
    }
    mx = red[0]; __syncthreads();

    float sum = 0.f;
    for (int p = tid; p < HWn; p += 1024) {
        float ex = __expf(se[p] - mx);
        se[p] = ex;
        sum += ex;
    }
    red[tid] = sum; __syncthreads();
    for (int s = 512; s; s >>= 1) {
        if (tid < s) red[tid] += red[tid + s];
        __syncthreads();
    }
    sum = red[0]; __syncthreads();

    const float inv = 1.f / sum;
    float* out_alpha = out + Bn * Cn;
    float* out_asum  = out + Bn * Cn + Bn * HWn;
    for (int p = tid; p < HWn; p += 1024) {
        float al = se[p] * inv;
        g_alpha[b * HWn + p] = al;
        out_alpha[b * HWn + p] = al;
        out_asum[b * HWn + p] = al + asum[b * HWn + p];
    }
}

// ---------------- context[b][c] = sum_p alpha[b][p] * cnn[b][c][p] ----------------
__global__ void k_context(const float* __restrict__ cnn,
                          float* __restrict__ out) {
    const int c = blockIdx.x, b = blockIdx.y, tid = threadIdx.x;
    const float4* row = (const float4*)(cnn + ((size_t)b * Cn + c) * HWn);
    const float4* al  = (const float4*)(g_alpha + b * HWn);
    float s = 0.f;
    #pragma unroll
    for (int it = 0; it < 4; it++) {
        int p = it * 256 + tid;
        float4 r = row[p], a = al[p];
        s = fmaf(a.x, r.x, s); s = fmaf(a.y, r.y, s);
        s = fmaf(a.z, r.z, s); s = fmaf(a.w, r.w, s);
    }
    #pragma unroll
    for (int off = 16; off; off >>= 1)
        s += __shfl_xor_sync(0xffffffffu, s, off);
    __shared__ float red[8];
    if ((tid & 31) == 0) red[tid >> 5] = s;
    __syncthreads();
    if (tid == 0) {
        float t = red[0] + red[1] + red[2] + red[3]
                + red[4] + red[5] + red[6] + red[7];
        out[b * Cn + c] = t;
    }
}

extern "C" void kernel_launch(void* const* d_in, const int* in_sizes, int n_in,
                              void* d_out, int out_size) {
    const float* cnn     = (const float*)d_in[0];   // [16,684,32,128]
    const float* cft     = (const float*)d_in[1];   // [16,512,32,128]
    const float* hidden  = (const float*)d_in[2];   // [16,256]
    const float* asum    = (const float*)d_in[3];   // [16,1,32,128]
    const int*   mask    = (const int*)  d_in[4];   // [16,1,32,128]
    const float* cmt     = (const float*)d_in[5];   // [16,32,128,512]
    const float* Wh      = (const float*)d_in[6];   // [512,256]
    const float* bh      = (const float*)d_in[7];   // [512]
    const float* Wconv   = (const float*)d_in[8];   // [512,1,11,11]
    const float* Wattn   = (const float*)d_in[9];   // [512,512]
    const float* Walpha  = (const float*)d_in[10];  // [1,512]
    // d_in[11] = b_alpha: softmax-invariant, skipped

    float* out = (float*)d_out; // [ context 16*684 | alpha 16*4096 | alpha_sum_new 16*4096 ]

    cudaFuncSetAttribute(k_energy, cudaFuncAttributeMaxDynamicSharedMemorySize, SM_TOT);

    k_prep<<<48, 256>>>(hidden, Wh, bh, Wattn, Wconv);
    k_energy<<<dim3(2, Hn, Bn), 256, SM_TOT>>>(cft, cmt, asum, Walpha);
    k_softmax<<<Bn, 1024>>>(asum, mask, out);
    k_context<<<dim3(Cn, Bn), 256>>>(cnn, out);
}

// round 6
// speedup vs baseline: 4.3144x; 1.2486x over previous
#include <cuda_runtime.h>
#include <cuda_bf16.h>
#include <math.h>
#include <math_constants.h>
#include <cstdint>

#define Bn  16
#define Cn  684
#define Hn  32
#define Wn  128
#define HIDn 256
#define An  512
#define HWn 4096
#define NTAP 121

// ---- scratch (device globals; no allocation allowed) ----
__device__ float    g_query[Bn * An];          // [b][a]
__device__ uint32_t g_weffb[An * 64];          // bf16x2 pairs: [a][tap-pair], taps padded to 128
__device__ float    g_epart[2 * Bn * HWn];     // [half][b][pos]
__device__ float    g_energy[Bn * HWn];        // combined masked energy
__device__ float    g_alpha[Bn * HWn];
__device__ float    g_pm[Bn * 4], g_ps[Bn * 4];  // per-quarter max / sumexp

// k_energy SMEM layout (bytes)
#define LDX 136
#define LDW 136
#define SM_X 0
#define SM_W 34816
#define SM_QWA 104448
#define SM_TOT 106496

__device__ __forceinline__ float fast_tanh(float x) {
    float y;
    asm("tanh.approx.f32 %0, %1;" : "=f"(y) : "f"(x));
    return y;
}

__device__ __forceinline__ uint32_t smem_u32(const void* p) {
    uint32_t a;
    asm("{ .reg .u64 t; cvta.to.shared.u64 t, %1; cvt.u32.u64 %0, t; }" : "=r"(a) : "l"(p));
    return a;
}

// ---------------- fused prep: query (blocks 0-15) + weff (blocks 16-143, 4 a-rows each) ----------------
__global__ void k_prep(const float* __restrict__ hidden,
                       const float* __restrict__ Wh,
                       const float* __restrict__ bh,
                       const float* __restrict__ Wattn,
                       const float* __restrict__ Wconv) {
    __shared__ float sa[4 * 512];
    const int tid = threadIdx.x;
    if (blockIdx.x < 16) {
        const int b = blockIdx.x;
        __shared__ float sh[HIDn];
        if (tid < HIDn) sh[tid] = hidden[b * HIDn + tid];
        __syncthreads();
        for (int a = tid; a < An; a += 256) {
            float s = bh[a];
            const float* w = Wh + (size_t)a * HIDn;
            #pragma unroll 8
            for (int k = 0; k < HIDn; k++) s = fmaf(w[k], sh[k], s);
            g_query[b * An + a] = s;
        }
    } else {
        const int chunk = blockIdx.x - 16;      // 0..127, 4 a-rows each
        for (int i = tid; i < 4 * 512; i += 256)
            sa[i] = Wattn[(size_t)chunk * 4 * 512 + i];
        __syncthreads();
        // one bf16x2 output pair per thread: o = tid -> (al, pr)
        const int al = tid >> 6, pr = tid & 63;
        float v0 = 0.f, v1 = 0.f;
        const int t0 = pr * 2, t1 = pr * 2 + 1;
        if (t0 < NTAP) {
            #pragma unroll 8
            for (int k = 0; k < 512; k++)
                v0 = fmaf(sa[al * 512 + k], __ldg(&Wconv[(size_t)k * NTAP + t0]), v0);
        }
        if (t1 < NTAP) {
            #pragma unroll 8
            for (int k = 0; k < 512; k++)
                v1 = fmaf(sa[al * 512 + k], __ldg(&Wconv[(size_t)k * NTAP + t1]), v1);
        }
        uint32_t lo = (uint32_t)__bfloat16_as_ushort(__float2bfloat16(v0));
        uint32_t hi = (uint32_t)__bfloat16_as_ushort(__float2bfloat16(v1));
        g_weffb[(chunk * 4 + al) * 64 + pr] = lo | (hi << 16);
    }
}

// ---------------- energy: mma.sync m16n8k16, pipelined loads, register epilogue ----------------
// grid (2 a-halves, H, B), 256 threads (8 warps). Warp wid owns positions [16*wid, 16*wid+16).
__global__ void __launch_bounds__(256, 2) k_energy(
    const float* __restrict__ cft,     // [b, A, h, w]
    const float* __restrict__ cmt,     // [b, h, w, A]
    const float* __restrict__ asum,    // [b, 1, h, w]
    const float* __restrict__ walpha)  // [A]
{
    extern __shared__ char smem[];
    __nv_bfloat16* Xsm = (__nv_bfloat16*)(smem + SM_X);
    __nv_bfloat16* Wsm = (__nv_bfloat16*)(smem + SM_W);
    float2*        QWA = (float2*)(smem + SM_QWA);

    const int half = blockIdx.x, h = blockIdx.y, b = blockIdx.z;
    const int tid = threadIdx.x, wid = tid >> 5, lane = tid & 31;
    const int g = lane >> 2, tig = lane & 3;

    // ---- stage X = im2col(asum) [128 pos x 128 taps] bf16 ----
    const float* arow = asum + (size_t)b * HWn;
    for (int o = tid; o < 128 * 64; o += 256) {
        int mm = o >> 6, pr = o & 63;
        uint32_t packed = 0;
        #pragma unroll
        for (int hf = 0; hf < 2; hf++) {
            int k = pr * 2 + hf;
            float v = 0.f;
            if (k < NTAP) {
                int i = k / 11, j = k % 11;
                int gh = h - 5 + i, gw = mm - 5 + j;
                if (gh >= 0 && gh < Hn && gw >= 0 && gw < Wn)
                    v = arow[gh * Wn + gw];
            }
            packed |= ((uint32_t)__bfloat16_as_ushort(__float2bfloat16(v))) << (16 * hf);
        }
        *(uint32_t*)((char*)Xsm + mm * (LDX * 2) + pr * 4) = packed;
    }
    // ---- stage W half: 256 a-rows x 128 taps bf16 ----
    const uint4* wsrc = (const uint4*)(g_weffb + (size_t)half * 256 * 64);
    for (int o = tid; o < 4096; o += 256) {
        int a = o >> 4, q = o & 15;
        *(uint4*)((char*)Wsm + a * (LDW * 2) + q * 16) = wsrc[o];
    }
    // ---- stage (query, walpha) pairs for this a-half ----
    for (int i = tid; i < 256; i += 256)
        QWA[i] = make_float2(g_query[b * An + half * 256 + i], walpha[half * 256 + i]);
    __syncthreads();

    // ---- B fragments (X) once: [nh][kk][2] ----
    const int pos0 = wid * 16;
    uint32_t bf[2][8][2];
    #pragma unroll
    for (int nh = 0; nh < 2; nh++) {
        const char* xrow = (const char*)Xsm + (pos0 + nh * 8 + g) * (LDX * 2);
        #pragma unroll
        for (int kk = 0; kk < 8; kk++) {
            bf[nh][kk][0] = *(const uint32_t*)(xrow + (kk * 16 + tig * 2) * 2);
            bf[nh][kk][1] = *(const uint32_t*)(xrow + (kk * 16 + tig * 2 + 8) * 2);
        }
    }

    const uint32_t a_base = smem_u32(Wsm) + (uint32_t)(lane & 15) * (LDW * 2) + (uint32_t)(lane >> 4) * 16;

    const float* cft_b = cft + ((size_t)b * An + half * 256) * (Hn * Wn) + h * Wn;
    const float* cmt_b = cmt + (((size_t)b * Hn + h) * Wn) * An + half * 256;
    const size_t HW = (size_t)Hn * Wn;

    // double-buffered epilogue operands
    float2 cfb[2][2][2];   // [buf][nh][aoff/8]
    float  cmb[2][2][4];   // [buf][nh][c]

    auto load_ops = [&](int buf, int A0L) {
        #pragma unroll
        for (int nh = 0; nh < 2; nh++) {
            const float* p = cft_b + (size_t)(A0L + g) * HW + pos0 + nh * 8 + tig * 2;
            cfb[buf][nh][0] = *(const float2*)p;
            cfb[buf][nh][1] = *(const float2*)(p + 8 * HW);
        }
        #pragma unroll
        for (int nh = 0; nh < 2; nh++) {
            const float* p = cmt_b + (size_t)(pos0 + nh * 8 + tig * 2) * An + A0L + g;
            cmb[buf][nh][0] = __ldg(p);
            cmb[buf][nh][1] = __ldg(p + An);
            cmb[buf][nh][2] = __ldg(p + 8);
            cmb[buf][nh][3] = __ldg(p + An + 8);
        }
    };

    load_ops(0, 0);   // prologue

    float epos[4] = {0.f, 0.f, 0.f, 0.f};

    #pragma unroll
    for (int mt = 0; mt < 16; mt++) {
        const int A0 = mt * 16;
        const int cur = mt & 1, nxt = cur ^ 1;

        // prefetch next iteration's operands (full-iteration load->use distance)
        load_ops(nxt, (mt < 15) ? A0 + 16 : A0);

        const float2 qw0 = QWA[A0 + g], qw1 = QWA[A0 + g + 8];

        // GEMM: two n-halves, 8 k-steps
        float c0[4] = {0.f, 0.f, 0.f, 0.f};
        float c1[4] = {0.f, 0.f, 0.f, 0.f};
        #pragma unroll
        for (int kk = 0; kk < 8; kk++) {
            uint32_t a0r, a1r, a2r, a3r;
            uint32_t addr = a_base + (uint32_t)A0 * (LDW * 2) + (uint32_t)(kk * 32);
            asm volatile("ldmatrix.sync.aligned.m8n8.x4.shared.b16 {%0,%1,%2,%3}, [%4];"
                         : "=r"(a0r), "=r"(a1r), "=r"(a2r), "=r"(a3r) : "r"(addr));
            asm volatile("mma.sync.aligned.m16n8k16.row.col.f32.bf16.bf16.f32 "
                         "{%0,%1,%2,%3}, {%4,%5,%6,%7}, {%8,%9}, {%0,%1,%2,%3};"
                         : "+f"(c0[0]), "+f"(c0[1]), "+f"(c0[2]), "+f"(c0[3])
                         : "r"(a0r), "r"(a1r), "r"(a2r), "r"(a3r),
                           "r"(bf[0][kk][0]), "r"(bf[0][kk][1]));
            asm volatile("mma.sync.aligned.m16n8k16.row.col.f32.bf16.bf16.f32 "
                         "{%0,%1,%2,%3}, {%4,%5,%6,%7}, {%8,%9}, {%0,%1,%2,%3};"
                         : "+f"(c1[0]), "+f"(c1[1]), "+f"(c1[2]), "+f"(c1[3])
                         : "r"(a0r), "r"(a1r), "r"(a2r), "r"(a3r),
                           "r"(bf[1][kk][0]), "r"(bf[1][kk][1]));
        }

        // register-resident epilogue on buffer 'cur'
        {
            float s;
            s = c0[0] + cfb[cur][0][0].x + cmb[cur][0][0] + qw0.x; epos[0] = fmaf(qw0.y, fast_tanh(s), epos[0]);
            s = c0[1] + cfb[cur][0][0].y + cmb[cur][0][1] + qw0.x; epos[1] = fmaf(qw0.y, fast_tanh(s), epos[1]);
            s = c0[2] + cfb[cur][0][1].x + cmb[cur][0][2] + qw1.x; epos[0] = fmaf(qw1.y, fast_tanh(s), epos[0]);
            s = c0[3] + cfb[cur][0][1].y + cmb[cur][0][3] + qw1.x; epos[1] = fmaf(qw1.y, fast_tanh(s), epos[1]);
            s = c1[0] + cfb[cur][1][0].x + cmb[cur][1][0] + qw0.x; epos[2] = fmaf(qw0.y, fast_tanh(s), epos[2]);
            s = c1[1] + cfb[cur][1][0].y + cmb[cur][1][1] + qw0.x; epos[3] = fmaf(qw0.y, fast_tanh(s), epos[3]);
            s = c1[2] + cfb[cur][1][1].x + cmb[cur][1][2] + qw1.x; epos[2] = fmaf(qw1.y, fast_tanh(s), epos[2]);
            s = c1[3] + cfb[cur][1][1].y + cmb[cur][1][3] + qw1.x; epos[3] = fmaf(qw1.y, fast_tanh(s), epos[3]);
        }
    }

    // reduce over the 8 g-lanes (lane bits 2-4)
    #pragma unroll
    for (int j = 0; j < 4; j++) {
        epos[j] += __shfl_xor_sync(0xffffffffu, epos[j], 4);
        epos[j] += __shfl_xor_sync(0xffffffffu, epos[j], 8);
        epos[j] += __shfl_xor_sync(0xffffffffu, epos[j], 16);
    }
    if (lane < 4) {
        float* ep = g_epart + ((size_t)half * Bn + b) * HWn + h * Wn + pos0;
        ep[tig * 2]         = epos[0];
        ep[tig * 2 + 1]     = epos[1];
        ep[8 + tig * 2]     = epos[2];
        ep[8 + tig * 2 + 1] = epos[3];
    }
}

// ---------------- softmax stage 1: per-(batch, quarter) max + sumexp ----------------
__global__ void k_sm1(const int* __restrict__ mask) {
    __shared__ float red[256];
    const int b = blockIdx.x, qt = blockIdx.y, tid = threadIdx.x;
    const int p0 = qt * 1024;

    float e4[4];
    float mx = -CUDART_INF_F;
    #pragma unroll
    for (int i = 0; i < 4; i++) {
        int p = p0 + i * 256 + tid;
        float e = g_epart[b * HWn + p] + g_epart[(Bn + b) * HWn + p];
        if (mask[b * HWn + p] == 0) e = -CUDART_INF_F;
        e4[i] = e;
        g_energy[b * HWn + p] = e;
        mx = fmaxf(mx, e);
    }
    red[tid] = mx; __syncthreads();
    for (int s = 128; s; s >>= 1) {
        if (tid < s) red[tid] = fmaxf(red[tid], red[tid + s]);
        __syncthreads();
    }
    mx = red[0]; __syncthreads();

    float sum = 0.f;
    #pragma unroll
    for (int i = 0; i < 4; i++) sum += __expf(e4[i] - mx);
    red[tid] = sum; __syncthreads();
    for (int s = 128; s; s >>= 1) {
        if (tid < s) red[tid] += red[tid + s];
        __syncthreads();
    }
    if (tid == 0) { g_pm[b * 4 + qt] = mx; g_ps[b * 4 + qt] = red[0]; }
}

// ---------------- softmax stage 2: combine + write alpha / alpha_sum_new ----------------
__global__ void k_sm2(const float* __restrict__ asum, float* __restrict__ out) {
    const int b = blockIdx.x, qt = blockIdx.y, tid = threadIdx.x;
    const int p0 = qt * 1024;

    float m0 = g_pm[b * 4 + 0], m1 = g_pm[b * 4 + 1];
    float m2 = g_pm[b * 4 + 2], m3 = g_pm[b * 4 + 3];
    float m = fmaxf(fmaxf(m0, m1), fmaxf(m2, m3));
    float s = g_ps[b * 4 + 0] * __expf(m0 - m) + g_ps[b * 4 + 1] * __expf(m1 - m)
            + g_ps[b * 4 + 2] * __expf(m2 - m) + g_ps[b * 4 + 3] * __expf(m3 - m);
    const float inv = 1.f / s;

    float* out_alpha = out + Bn * Cn;
    float* out_asum  = out + Bn * Cn + Bn * HWn;
    #pragma unroll
    for (int i = 0; i < 4; i++) {
        int p = p0 + i * 256 + tid;
        float al = __expf(g_energy[b * HWn + p] - m) * inv;
        g_alpha[b * HWn + p] = al;
        out_alpha[b * HWn + p] = al;
        out_asum[b * HWn + p] = al + asum[b * HWn + p];
    }
}

// ---------------- context[b][c] = sum_p alpha[b][p] * cnn[b][c][p] ----------------
__global__ void k_context(const float* __restrict__ cnn,
                          float* __restrict__ out) {
    const int c = blockIdx.x, b = blockIdx.y, tid = threadIdx.x;
    const float4* row = (const float4*)(cnn + ((size_t)b * Cn + c) * HWn);
    const float4* al  = (const float4*)(g_alpha + b * HWn);
    float s = 0.f;
    #pragma unroll
    for (int it = 0; it < 4; it++) {
        int p = it * 256 + tid;
        float4 r = row[p], a = al[p];
        s = fmaf(a.x, r.x, s); s = fmaf(a.y, r.y, s);
        s = fmaf(a.z, r.z, s); s = fmaf(a.w, r.w, s);
    }
    #pragma unroll
    for (int off = 16; off; off >>= 1)
        s += __shfl_xor_sync(0xffffffffu, s, off);
    __shared__ float red[8];
    if ((tid & 31) == 0) red[tid >> 5] = s;
    __syncthreads();
    if (tid == 0) {
        float t = red[0] + red[1] + red[2] + red[3]
                + red[4] + red[5] + red[6] + red[7];
        out[b * Cn + c] = t;
    }
}

extern "C" void kernel_launch(void* const* d_in, const int* in_sizes, int n_in,
                              void* d_out, int out_size) {
    const float* cnn     = (const float*)d_in[0];   // [16,684,32,128]
    const float* cft     = (const float*)d_in[1];   // [16,512,32,128]
    const float* hidden  = (const float*)d_in[2];   // [16,256]
    const float* asum    = (const float*)d_in[3];   // [16,1,32,128]
    const int*   mask    = (const int*)  d_in[4];   // [16,1,32,128]
    const float* cmt     = (const float*)d_in[5];   // [16,32,128,512]
    const float* Wh      = (const float*)d_in[6];   // [512,256]
    const float* bh      = (const float*)d_in[7];   // [512]
    const float* Wconv   = (const float*)d_in[8];   // [512,1,11,11]
    const float* Wattn   = (const float*)d_in[9];   // [512,512]
    const float* Walpha  = (const float*)d_in[10];  // [1,512]
    // d_in[11] = b_alpha: softmax-invariant, skipped

    float* out = (float*)d_out; // [ context 16*684 | alpha 16*4096 | alpha_sum_new 16*4096 ]

    cudaFuncSetAttribute(k_energy, cudaFuncAttributeMaxDynamicSharedMemorySize, SM_TOT);

    k_prep<<<144, 256>>>(hidden, Wh, bh, Wattn, Wconv);
    k_energy<<<dim3(2, Hn, Bn), 256, SM_TOT>>>(cft, cmt, asum, Walpha);
    k_sm1<<<dim3(Bn, 4), 256>>>(mask);
    k_sm2<<<dim3(Bn, 4), 256>>>(asum, out);
    k_context<<<dim3(Cn, Bn), 256>>>(cnn, out);
}